// round 8
// baseline (speedup 1.0000x reference)
#include <cuda_runtime.h>
#include <cstdint>

// Problem constants
#define BB 8
#define TT 2048
#define CC 1024
#define HH 64

// k projection scratch, tf32-rounded bits, PAIR-INTERLEAVED columns:
// within each 8-col group, storage order is [0,4,1,5,2,6,3,7] so that the
// mma-pair (c, c+4) is adjacent (one LDS.64).
__device__ float g_kbuf[BB * TT * HH];
// W pre-converted to tf32 bits, same pair-interleave within 8-col k-groups
__device__ float g_wt[HH * CC];
// KV-split partials + per-row (m,l)
__device__ float g_part[256 * 64 * 64];
__device__ float g_stats[256 * 64 * 2];

// per-class item lists (within a batch), grouped by iteration count 8..1
// layout: [8]x8, [7]x10, [6]x10, [5]x10, [4]x4, [3]x2, [2]x2, [1]x2
__constant__ int c_it[48] = {
    46,47,25,27,28,29,30,31,
    44,45,17,19,20,21,22,23,24,26,
    42,43, 9,11,12,13,14,15,16,18,
    40,41, 1, 3, 4, 5, 6, 7, 8,10,
    38,39, 0, 2,
    36,37,
    34,35,
    32,33
};

// ---------------------------------------------------------------------------
// helpers
// ---------------------------------------------------------------------------
__device__ __forceinline__ uint32_t f2t(float x) {
    uint32_t u;
    asm("cvt.rna.tf32.f32 %0, %1;" : "=r"(u) : "f"(x));
    return u;
}

__device__ __forceinline__ void mma8(float* c, const uint32_t* a, const uint32_t* b) {
    asm volatile(
        "mma.sync.aligned.m16n8k8.row.col.f32.tf32.tf32.f32 "
        "{%0,%1,%2,%3}, {%4,%5,%6,%7}, {%8,%9}, {%0,%1,%2,%3};"
        : "+f"(c[0]), "+f"(c[1]), "+f"(c[2]), "+f"(c[3])
        : "r"(a[0]), "r"(a[1]), "r"(a[2]), "r"(a[3]), "r"(b[0]), "r"(b[1]));
}

__device__ __forceinline__ void cpa16(uint32_t dst, const void* src) {
    asm volatile("cp.async.cg.shared.global [%0], [%1], 16;" :: "r"(dst), "l"(src));
}
__device__ __forceinline__ void cpa_commit() {
    asm volatile("cp.async.commit_group;");
}

// ---------------------------------------------------------------------------
// Kernel 0: W [64,1024] fp32 -> tf32 bits, pair-interleaved in 8-col groups.
// ---------------------------------------------------------------------------
__global__ __launch_bounds__(256) void wconv_kernel(
    const float* __restrict__ W, float* __restrict__ wt)
{
    const int row = blockIdx.x;            // 64 rows
    const int t = threadIdx.x;             // 256 threads, 4 cols each
    float4 v = *(const float4*)(W + (size_t)row * CC + t * 4);
    int g = t >> 1;
    int w8b = (t & 1) * 4;                 // 0 or 4
    float* dst = wt + (size_t)row * CC + g * 8;
    dst[2 * ((w8b + 0) & 3) + ((w8b + 0) >> 2)] = __uint_as_float(f2t(v.x));
    dst[2 * ((w8b + 1) & 3) + ((w8b + 1) >> 2)] = __uint_as_float(f2t(v.y));
    dst[2 * ((w8b + 2) & 3) + ((w8b + 2) >> 2)] = __uint_as_float(f2t(v.z));
    dst[2 * ((w8b + 3) & 3) + ((w8b + 3) >> 2)] = __uint_as_float(f2t(v.w));
}

// ---------------------------------------------------------------------------
// Kernel 1: k = tf32(x @ W^T), interleaved output. 128 rows/block (grid 128),
// 256 threads = 8 warps, 2 m-tiles per warp; W frags are LDS.64, no cvt.
// 4-stage cp.async pipeline over 32-col K chunks.
// ---------------------------------------------------------------------------
#define PROJ_M 128
#define PKC 32
#define XS 36
#define WTS 40
#define PST 4
#define PROJ_XSF (PROJ_M * XS)               // 4608 floats per x stage
#define PROJ_WSF (HH * WTS)                  // 2560 floats per W stage
#define PROJ_STF (PROJ_XSF + PROJ_WSF)       // 7168
#define PROJ_SMEM_BYTES (PST * PROJ_STF * 4) // 114688

__global__ __launch_bounds__(256, 1) void proj_kernel(
    const float* __restrict__ x, const float* __restrict__ wt, float* __restrict__ ko)
{
    extern __shared__ float psm[];
    const uint32_t sba = (uint32_t)__cvta_generic_to_shared(psm);

    const int tid = threadIdx.x;
    const int row0 = blockIdx.x * PROJ_M;
    const int w = tid >> 5, lane = tid & 31, gid = lane >> 2, t4 = lane & 3;
    const int mw = w & 3;      // m-group: 32 rows at 32*mw
    const int nh = w >> 2;     // n-group: 32 cols at 32*nh

    const int xr[4] = { tid >> 3, (tid + 256) >> 3, (tid + 512) >> 3, (tid + 768) >> 3 };
    const int xc = tid & 7;
    const int wr0 = tid >> 3, wr1 = (tid + 256) >> 3;
    const int wc = tid & 7;

    auto issue_chunk = [&](int ci) {
        int st = ci & (PST - 1);
        uint32_t dx = sba + (uint32_t)(st * PROJ_STF) * 4;
        uint32_t dw = dx + (uint32_t)PROJ_XSF * 4;
        const float* xsrc = x + (size_t)row0 * CC + ci * PKC;
        const float* wsrc = wt + ci * PKC;
        #pragma unroll
        for (int t = 0; t < 4; t++)
            cpa16(dx + (uint32_t)(xr[t] * XS + xc * 4) * 4,
                  xsrc + (size_t)xr[t] * CC + xc * 4);
        cpa16(dw + (uint32_t)(wr0 * WTS + wc * 4) * 4, wsrc + (size_t)wr0 * CC + wc * 4);
        cpa16(dw + (uint32_t)(wr1 * WTS + wc * 4) * 4, wsrc + (size_t)wr1 * CC + wc * 4);
    };

    float acc[2][4][4];
    #pragma unroll
    for (int m = 0; m < 2; m++)
        #pragma unroll
        for (int i = 0; i < 4; i++)
            #pragma unroll
            for (int l = 0; l < 4; l++) acc[m][i][l] = 0.f;

    issue_chunk(0); cpa_commit();
    issue_chunk(1); cpa_commit();
    issue_chunk(2); cpa_commit();

    const int NCHUNK = CC / PKC;  // 32
    for (int ci = 0; ci < NCHUNK; ci++) {
        asm volatile("cp.async.wait_group 2;");
        __syncthreads();
        if (ci + 3 < NCHUNK) issue_chunk(ci + 3);
        cpa_commit();

        const float* bx = psm + (ci & (PST - 1)) * PROJ_STF;
        const float* bw = bx + PROJ_XSF;
        #pragma unroll
        for (int k0 = 0; k0 < PKC; k0 += 8) {
            uint32_t a[2][4];
            #pragma unroll
            for (int mt = 0; mt < 2; mt++) {
                const float* pq = bx + (32 * mw + 16 * mt + gid) * XS + k0 + t4;
                a[mt][0] = f2t(pq[0]);
                a[mt][1] = f2t(pq[8 * XS]);
                a[mt][2] = f2t(pq[4]);
                a[mt][3] = f2t(pq[8 * XS + 4]);
            }
            #pragma unroll
            for (int nt = 0; nt < 4; nt++) {
                float2 kv = *(const float2*)&bw[(32 * nh + 8 * nt + gid) * WTS + k0 + 2 * t4];
                uint32_t bb[2] = { __float_as_uint(kv.x), __float_as_uint(kv.y) };
                mma8(acc[0][nt], a[0], bb);
                mma8(acc[1][nt], a[1], bb);
            }
        }
    }

    const int pe = 2 * ((2 * t4) & 3) + ((2 * t4) >> 2);
    const int po = 2 * ((2 * t4 + 1) & 3) + ((2 * t4 + 1) >> 2);
    #pragma unroll
    for (int mt = 0; mt < 2; mt++)
        #pragma unroll
        for (int nt = 0; nt < 4; nt++) {
            int r = row0 + 32 * mw + 16 * mt + gid;
            int cb = 32 * nh + 8 * nt;
            ko[(size_t)r * HH + cb + pe]       = __uint_as_float(f2t(acc[mt][nt][0]));
            ko[(size_t)r * HH + cb + po]       = __uint_as_float(f2t(acc[mt][nt][1]));
            ko[(size_t)(r + 8) * HH + cb + pe] = __uint_as_float(f2t(acc[mt][nt][2]));
            ko[(size_t)(r + 8) * HH + cb + po] = __uint_as_float(f2t(acc[mt][nt][3]));
        }
}

// ---------------------------------------------------------------------------
// Kernel 2: causal flash attention, KV-split, interleaved k-buffer.
// 128 threads, 3 CTAs/SM. Blocks bid, bid+148, bid+296 share an SM
// (LUT[bid % 148]); items are bin-packed so each SM's total iters ~15.
// ---------------------------------------------------------------------------
#define QT 64
#define KT 128
#define QS 72
#define KS 72
#define SCALE 0.03125f

#define ATTN_SMEM_FLOATS (QT * QS + KT * KS)
#define ATTN_SMEM_BYTES  (ATTN_SMEM_FLOATS * 4)

__global__ __launch_bounds__(128, 3) void attn_kernel(
    const float* __restrict__ kb, float* __restrict__ out,
    float* __restrict__ part, float* __restrict__ stats)
{
    extern __shared__ float sm[];
    float* sQ = sm;             // QT*QS
    float* sK = sQ + QT * QS;   // KT*KS

    const int tid = threadIdx.x;
    const int bid = blockIdx.x;

    // ---- bin-packed schedule: (wave, slot) -> (class, instance) ----
    int wave, slot;
    if (bid < 148)      { wave = 0; slot = bid; }
    else if (bid < 296) { wave = 1; slot = bid - 148; }
    else                { wave = 2; slot = bid - 296; }

    int cls, inst;
    if (wave == 0) {
        if (slot < 4)       { cls = 8; inst = slot; }
        else if (slot < 24) { cls = 7; inst = slot - 4; }
        else if (slot < 84) { cls = 6; inst = slot - 24; }
        else if (slot < 88) { cls = 5; inst = slot - 84; }
        else                { cls = 8; inst = 4 + slot - 88; }
    } else if (wave == 1) {
        if (slot < 20)      { cls = 6; inst = 60 + slot; }
        else if (slot < 88) { cls = 5; inst = 4 + slot - 20; }
        else                { cls = 7; inst = 20 + slot - 88; }
    } else {
        if (slot < 4)       { cls = 1; inst = slot; }
        else if (slot < 20) { cls = 2; inst = slot - 4; }
        else if (slot < 24) { cls = 3; inst = slot - 20; }
        else if (slot < 56) { cls = 4; inst = slot - 24; }
        else if (slot < 68) { cls = 3; inst = 4 + slot - 56; }
        else if (slot < 80) { cls = 1; inst = 4 + slot - 68; }
        else                { cls = 5; inst = 72 + slot - 80; }
    }

    int off, n;
    switch (cls) {
        case 8: off = 0;  n = 8;  break;
        case 7: off = 8;  n = 10; break;
        case 6: off = 18; n = 10; break;
        case 5: off = 28; n = 10; break;
        case 4: off = 38; n = 4;  break;
        case 3: off = 42; n = 2;  break;
        case 2: off = 44; n = 2;  break;
        default: off = 46; n = 2; break;
    }
    const int b = inst / n;
    const int item = c_it[off + inst - b * n];

    int qt, j0, j1, split;
    bool is_split;
    if (item < 32) {
        qt = 16 + (item >> 1);
        split = item & 1;
        int jm = qt >> 1;
        int h = (jm + 1) >> 1;
        if (split == 0) { j0 = 0; j1 = h - 1; }
        else            { j0 = h; j1 = jm; }
        is_split = true;
    } else {
        qt = item - 32;
        split = 0;
        j0 = 0; j1 = qt >> 1;
        is_split = false;
    }
    const int jmaskg = qt >> 1;
    const int qrow0 = qt * QT;
    const float* kbase = kb + (size_t)b * TT * HH;

    const int w = tid >> 5, lane = tid & 31, gid = lane >> 2, t4 = lane & 3;
    const int srcA = (lane & ~3) | (t4 >> 1);
    const int srcB = srcA + 2;
    const bool odd = (t4 & 1);
    const int pvoff = 2 * (gid & 3) + (gid >> 2);

    // load Q tile (scaled; power-of-two scale keeps tf32 bits)
    #pragma unroll
    for (int i = tid; i < QT * (HH / 4); i += 128) {
        int r = i >> 4, c4 = i & 15;
        float4 v = *(const float4*)(kbase + (size_t)(qrow0 + r) * HH + c4 * 4);
        v.x *= SCALE; v.y *= SCALE; v.z *= SCALE; v.w *= SCALE;
        *(float4*)&sQ[r * QS + c4 * 4] = v;
    }

    float m0 = -1e30f, m1 = -1e30f, l0 = 0.f, l1 = 0.f;
    const int rg0 = qrow0 + 16 * w + gid;
    const int rg1 = rg0 + 8;

    float o[8][4];
    #pragma unroll
    for (int i = 0; i < 8; i++)
        #pragma unroll
        for (int l = 0; l < 4; l++) o[i][l] = 0.f;

    for (int j = j0; j <= j1; j++) {
        __syncthreads();
        #pragma unroll
        for (int i = tid; i < KT * (HH / 4); i += 128) {
            int r = i >> 4, c4 = i & 15;
            *(float4*)&sK[r * KS + c4 * 4] =
                *(const float4*)(kbase + (size_t)(j * KT + r) * HH + c4 * 4);
        }
        __syncthreads();

        // ---- S = Q K^T ----
        float s[16][4];
        #pragma unroll
        for (int nt = 0; nt < 16; nt++)
            #pragma unroll
            for (int l = 0; l < 4; l++) s[nt][l] = 0.f;

        #pragma unroll
        for (int k0 = 0; k0 < HH; k0 += 8) {
            uint32_t a[4];
            float2 qa = *(const float2*)&sQ[(16 * w + gid) * QS + k0 + 2 * t4];
            float2 qb = *(const float2*)&sQ[(16 * w + gid + 8) * QS + k0 + 2 * t4];
            a[0] = __float_as_uint(qa.x);
            a[1] = __float_as_uint(qb.x);
            a[2] = __float_as_uint(qa.y);
            a[3] = __float_as_uint(qb.y);
            #pragma unroll
            for (int nt = 0; nt < 16; nt++) {
                float2 kv = *(const float2*)&sK[(8 * nt + gid) * KS + k0 + 2 * t4];
                uint32_t bb[2] = { __float_as_uint(kv.x), __float_as_uint(kv.y) };
                mma8(s[nt], a, bb);
            }
        }

        // ---- causal mask (diagonal tile only) ----
        if (j == jmaskg) {
            #pragma unroll
            for (int nt = 0; nt < 16; nt++) {
                int kc = j * KT + 8 * nt + 2 * t4;
                if (kc     > rg0) s[nt][0] = -1e30f;
                if (kc + 1 > rg0) s[nt][1] = -1e30f;
                if (kc     > rg1) s[nt][2] = -1e30f;
                if (kc + 1 > rg1) s[nt][3] = -1e30f;
            }
        }

        // ---- online softmax ----
        float mx0 = -1e30f, mx1 = -1e30f;
        #pragma unroll
        for (int nt = 0; nt < 16; nt++) {
            mx0 = fmaxf(mx0, fmaxf(s[nt][0], s[nt][1]));
            mx1 = fmaxf(mx1, fmaxf(s[nt][2], s[nt][3]));
        }
        mx0 = fmaxf(mx0, __shfl_xor_sync(0xffffffffu, mx0, 1));
        mx0 = fmaxf(mx0, __shfl_xor_sync(0xffffffffu, mx0, 2));
        mx1 = fmaxf(mx1, __shfl_xor_sync(0xffffffffu, mx1, 1));
        mx1 = fmaxf(mx1, __shfl_xor_sync(0xffffffffu, mx1, 2));

        float mn0 = fmaxf(m0, mx0), mn1 = fmaxf(m1, mx1);
        float al0 = __expf(m0 - mn0), al1 = __expf(m1 - mn1);
        m0 = mn0; m1 = mn1;

        float sum0 = 0.f, sum1 = 0.f;
        #pragma unroll
        for (int nt = 0; nt < 16; nt++) {
            s[nt][0] = __expf(s[nt][0] - mn0);
            s[nt][1] = __expf(s[nt][1] - mn0);
            s[nt][2] = __expf(s[nt][2] - mn1);
            s[nt][3] = __expf(s[nt][3] - mn1);
            sum0 += s[nt][0] + s[nt][1];
            sum1 += s[nt][2] + s[nt][3];
        }
        sum0 += __shfl_xor_sync(0xffffffffu, sum0, 1);
        sum0 += __shfl_xor_sync(0xffffffffu, sum0, 2);
        sum1 += __shfl_xor_sync(0xffffffffu, sum1, 1);
        sum1 += __shfl_xor_sync(0xffffffffu, sum1, 2);
        l0 = l0 * al0 + sum0;
        l1 = l1 * al1 + sum1;

        #pragma unroll
        for (int nt = 0; nt < 8; nt++) {
            o[nt][0] *= al0; o[nt][1] *= al0; o[nt][2] *= al1; o[nt][3] *= al1;
        }

        // ---- O += P V ----
        #pragma unroll
        for (int kk = 0; kk < 16; kk++) {
            float v00 = __shfl_sync(0xffffffffu, s[kk][0], srcA);
            float v01 = __shfl_sync(0xffffffffu, s[kk][1], srcA);
            float v10 = __shfl_sync(0xffffffffu, s[kk][0], srcB);
            float v11 = __shfl_sync(0xffffffffu, s[kk][1], srcB);
            float v20 = __shfl_sync(0xffffffffu, s[kk][2], srcA);
            float v21 = __shfl_sync(0xffffffffu, s[kk][3], srcA);
            float v30 = __shfl_sync(0xffffffffu, s[kk][2], srcB);
            float v31 = __shfl_sync(0xffffffffu, s[kk][3], srcB);
            uint32_t a[4];
            a[0] = f2t(odd ? v01 : v00);
            a[1] = f2t(odd ? v21 : v20);
            a[2] = f2t(odd ? v11 : v10);
            a[3] = f2t(odd ? v31 : v30);
            const float* rowp = sK + (8 * kk + t4) * KS + pvoff;
            #pragma unroll
            for (int nt = 0; nt < 8; nt++) {
                uint32_t bb[2] = { __float_as_uint(rowp[8 * nt]),
                                   __float_as_uint(rowp[8 * nt + 4 * KS]) };
                mma8(o[nt], a, bb);
            }
        }
    }

    if (!is_split) {
        float il0 = 1.f / l0, il1 = 1.f / l1;
        float* ob = out + (size_t)b * TT * HH;
        #pragma unroll
        for (int nt = 0; nt < 8; nt++) {
            int c = 8 * nt + 2 * t4;
            float2 r0v = { o[nt][0] * il0, o[nt][1] * il0 };
            float2 r1v = { o[nt][2] * il1, o[nt][3] * il1 };
            *(float2*)(ob + (size_t)rg0 * HH + c) = r0v;
            *(float2*)(ob + (size_t)rg1 * HH + c) = r1v;
        }
    } else {
        const int part_id = (b * 16 + (qt - 16)) * 2 + split;
        float* po = part + (size_t)part_id * (QT * HH);
        const int lr0 = 16 * w + gid, lr1 = lr0 + 8;
        #pragma unroll
        for (int nt = 0; nt < 8; nt++) {
            int c = 8 * nt + 2 * t4;
            float2 r0v = { o[nt][0], o[nt][1] };
            float2 r1v = { o[nt][2], o[nt][3] };
            *(float2*)(po + lr0 * HH + c) = r0v;
            *(float2*)(po + lr1 * HH + c) = r1v;
        }
        if (t4 == 0) {
            stats[part_id * 128 + lr0 * 2]     = m0;
            stats[part_id * 128 + lr0 * 2 + 1] = l0;
            stats[part_id * 128 + lr1 * 2]     = m1;
            stats[part_id * 128 + lr1 * 2 + 1] = l1;
        }
    }
}

// ---------------------------------------------------------------------------
// Kernel 3: merge KV-split partials. 256 blocks (half tile each), 128 threads,
// 4 independent float4-pairs per thread for MLP/latency hiding.
// ---------------------------------------------------------------------------
__global__ __launch_bounds__(128) void combine_kernel(
    const float* __restrict__ part, const float* __restrict__ stats,
    float* __restrict__ out)
{
    const int blk = blockIdx.x;          // 0..255
    const int idx = blk >> 1;            // tile id: b*16 + qt16
    const int half = blk & 1;            // rows [32*half, 32*half+32)
    const int b = idx >> 4, qt = 16 + (idx & 15);
    const int p0 = idx * 2, p1 = p0 + 1;
    __shared__ float a0s[32], a1s[32], invs[32];
    const int tid = threadIdx.x;
    if (tid < 32) {
        int r = half * 32 + tid;
        float2 s0 = *(const float2*)&stats[p0 * 128 + r * 2];
        float2 s1 = *(const float2*)&stats[p1 * 128 + r * 2];
        float m = fmaxf(s0.x, s1.x);
        float a0 = __expf(s0.x - m), a1 = __expf(s1.x - m);
        a0s[tid] = a0; a1s[tid] = a1;
        invs[tid] = 1.f / (a0 * s0.y + a1 * s1.y);
    }
    __syncthreads();
    const float4* P0 = (const float4*)(part + (size_t)p0 * (QT * HH)) + half * 512;
    const float4* P1 = (const float4*)(part + (size_t)p1 * (QT * HH)) + half * 512;
    float4* ob = (float4*)(out + ((size_t)b * TT + qt * QT + half * 32) * HH);
    #pragma unroll
    for (int k = 0; k < 4; k++) {
        int e = tid + k * 128;
        int r = e >> 4;
        float a0 = a0s[r], a1 = a1s[r], iv = invs[r];
        float4 u = P0[e], v = P1[e];
        float4 rres;
        rres.x = (a0 * u.x + a1 * v.x) * iv;
        rres.y = (a0 * u.y + a1 * v.y) * iv;
        rres.z = (a0 * u.z + a1 * v.z) * iv;
        rres.w = (a0 * u.w + a1 * v.w) * iv;
        ob[e] = rres;
    }
}

// ---------------------------------------------------------------------------
// launch
// ---------------------------------------------------------------------------
extern "C" void kernel_launch(void* const* d_in, const int* in_sizes, int n_in,
                              void* d_out, int out_size)
{
    const float* x = (const float*)d_in[0];   // [B, T, C]
    const float* W = (const float*)d_in[1];   // [H, C]
    float* out = (float*)d_out;               // [B, T, H]

    float *kbuf = nullptr, *wt = nullptr, *part = nullptr, *stats = nullptr;
    cudaGetSymbolAddress((void**)&kbuf, g_kbuf);
    cudaGetSymbolAddress((void**)&wt, g_wt);
    cudaGetSymbolAddress((void**)&part, g_part);
    cudaGetSymbolAddress((void**)&stats, g_stats);

    cudaFuncSetAttribute(proj_kernel, cudaFuncAttributeMaxDynamicSharedMemorySize,
                         PROJ_SMEM_BYTES);
    cudaFuncSetAttribute(attn_kernel, cudaFuncAttributeMaxDynamicSharedMemorySize,
                         ATTN_SMEM_BYTES);

    wconv_kernel<<<HH, 256>>>(W, wt);

    proj_kernel<<<(BB * TT) / PROJ_M, 256, PROJ_SMEM_BYTES>>>(x, wt, kbuf);

    attn_kernel<<<384, 128, ATTN_SMEM_BYTES>>>(kbuf, out, part, stats);

    combine_kernel<<<256, 128>>>(part, stats, out);
}

// round 9
// speedup vs baseline: 1.0704x; 1.0704x over previous
#include <cuda_runtime.h>
#include <cstdint>

// Problem constants
#define BB 8
#define TT 2048
#define CC 1024
#define HH 64

// k projection scratch, tf32-rounded bits, PAIR-INTERLEAVED columns:
// within each 8-col group, storage order is [0,4,1,5,2,6,3,7] so that the
// mma-pair (c, c+4) is adjacent (one LDS.64).
__device__ float g_kbuf[BB * TT * HH];
// W pre-converted to tf32 bits, same pair-interleave within 8-col k-groups
__device__ float g_wt[HH * CC];
// KV-split partials (split-0 half only): 128 pairs x 64 rows x 64 cols
__device__ float g_part[128 * 64 * 64];
// per-row (m, l) for split-0 partials
__device__ float g_stats[128 * 64 * 2];
// ready flags, one per split pair; zero-initialized at module load, and each
// consumer resets its flag to 0 after merging => invariant holds per replay
__device__ int g_flags[128];

// item order sorted by iteration count (descending), 48 items per batch
__constant__ int c_order[48] = {
    46,47,25,27,28,29,30,31,                 // 8 iters
    44,45,17,19,20,21,22,23,24,26,           // 7
    42,43, 9,11,12,13,14,15,16,18,           // 6
    40,41, 1, 3, 4, 5, 6, 7, 8,10,           // 5
    38,39, 0, 2,                             // 4
    36,37, 34,35, 32,33                      // 3,2,1
};

// ---------------------------------------------------------------------------
// helpers
// ---------------------------------------------------------------------------
__device__ __forceinline__ uint32_t f2t(float x) {
    uint32_t u;
    asm("cvt.rna.tf32.f32 %0, %1;" : "=r"(u) : "f"(x));
    return u;
}

__device__ __forceinline__ void mma8(float* c, const uint32_t* a, const uint32_t* b) {
    asm volatile(
        "mma.sync.aligned.m16n8k8.row.col.f32.tf32.tf32.f32 "
        "{%0,%1,%2,%3}, {%4,%5,%6,%7}, {%8,%9}, {%0,%1,%2,%3};"
        : "+f"(c[0]), "+f"(c[1]), "+f"(c[2]), "+f"(c[3])
        : "r"(a[0]), "r"(a[1]), "r"(a[2]), "r"(a[3]), "r"(b[0]), "r"(b[1]));
}

__device__ __forceinline__ void cpa16(uint32_t dst, const void* src) {
    asm volatile("cp.async.cg.shared.global [%0], [%1], 16;" :: "r"(dst), "l"(src));
}
__device__ __forceinline__ void cpa_commit() {
    asm volatile("cp.async.commit_group;");
}

// ---------------------------------------------------------------------------
// Kernel 0: W [64,1024] fp32 -> tf32 bits, pair-interleaved in 8-col groups.
// ---------------------------------------------------------------------------
__global__ __launch_bounds__(256) void wconv_kernel(
    const float* __restrict__ W, float* __restrict__ wt)
{
    const int row = blockIdx.x;            // 64 rows
    const int t = threadIdx.x;             // 256 threads, 4 cols each
    float4 v = *(const float4*)(W + (size_t)row * CC + t * 4);
    int g = t >> 1;
    int w8b = (t & 1) * 4;                 // 0 or 4
    float* dst = wt + (size_t)row * CC + g * 8;
    dst[2 * ((w8b + 0) & 3) + ((w8b + 0) >> 2)] = __uint_as_float(f2t(v.x));
    dst[2 * ((w8b + 1) & 3) + ((w8b + 1) >> 2)] = __uint_as_float(f2t(v.y));
    dst[2 * ((w8b + 2) & 3) + ((w8b + 2) >> 2)] = __uint_as_float(f2t(v.z));
    dst[2 * ((w8b + 3) & 3) + ((w8b + 3) >> 2)] = __uint_as_float(f2t(v.w));
}

// ---------------------------------------------------------------------------
// Kernel 1: k = tf32(x @ W^T), interleaved output. 128 rows/block (grid 128),
// 256 threads = 8 warps, 2 m-tiles per warp; W frags are LDS.64, no cvt.
// 4-stage cp.async pipeline over 32-col K chunks.
// ---------------------------------------------------------------------------
#define PROJ_M 128
#define PKC 32
#define XS 36
#define WTS 40
#define PST 4
#define PROJ_XSF (PROJ_M * XS)               // 4608 floats per x stage
#define PROJ_WSF (HH * WTS)                  // 2560 floats per W stage
#define PROJ_STF (PROJ_XSF + PROJ_WSF)       // 7168
#define PROJ_SMEM_BYTES (PST * PROJ_STF * 4) // 114688

__global__ __launch_bounds__(256, 1) void proj_kernel(
    const float* __restrict__ x, const float* __restrict__ wt, float* __restrict__ ko)
{
    extern __shared__ float psm[];
    const uint32_t sba = (uint32_t)__cvta_generic_to_shared(psm);

    const int tid = threadIdx.x;
    const int row0 = blockIdx.x * PROJ_M;
    const int w = tid >> 5, lane = tid & 31, gid = lane >> 2, t4 = lane & 3;
    const int mw = w & 3;      // m-group: 32 rows at 32*mw
    const int nh = w >> 2;     // n-group: 32 cols at 32*nh

    const int xr[4] = { tid >> 3, (tid + 256) >> 3, (tid + 512) >> 3, (tid + 768) >> 3 };
    const int xc = tid & 7;
    const int wr0 = tid >> 3, wr1 = (tid + 256) >> 3;
    const int wc = tid & 7;

    auto issue_chunk = [&](int ci) {
        int st = ci & (PST - 1);
        uint32_t dx = sba + (uint32_t)(st * PROJ_STF) * 4;
        uint32_t dw = dx + (uint32_t)PROJ_XSF * 4;
        const float* xsrc = x + (size_t)row0 * CC + ci * PKC;
        const float* wsrc = wt + ci * PKC;
        #pragma unroll
        for (int t = 0; t < 4; t++)
            cpa16(dx + (uint32_t)(xr[t] * XS + xc * 4) * 4,
                  xsrc + (size_t)xr[t] * CC + xc * 4);
        cpa16(dw + (uint32_t)(wr0 * WTS + wc * 4) * 4, wsrc + (size_t)wr0 * CC + wc * 4);
        cpa16(dw + (uint32_t)(wr1 * WTS + wc * 4) * 4, wsrc + (size_t)wr1 * CC + wc * 4);
    };

    float acc[2][4][4];
    #pragma unroll
    for (int m = 0; m < 2; m++)
        #pragma unroll
        for (int i = 0; i < 4; i++)
            #pragma unroll
            for (int l = 0; l < 4; l++) acc[m][i][l] = 0.f;

    issue_chunk(0); cpa_commit();
    issue_chunk(1); cpa_commit();
    issue_chunk(2); cpa_commit();

    const int NCHUNK = CC / PKC;  // 32
    for (int ci = 0; ci < NCHUNK; ci++) {
        asm volatile("cp.async.wait_group 2;");
        __syncthreads();
        if (ci + 3 < NCHUNK) issue_chunk(ci + 3);
        cpa_commit();

        const float* bx = psm + (ci & (PST - 1)) * PROJ_STF;
        const float* bw = bx + PROJ_XSF;
        #pragma unroll
        for (int k0 = 0; k0 < PKC; k0 += 8) {
            uint32_t a[2][4];
            #pragma unroll
            for (int mt = 0; mt < 2; mt++) {
                const float* pq = bx + (32 * mw + 16 * mt + gid) * XS + k0 + t4;
                a[mt][0] = f2t(pq[0]);
                a[mt][1] = f2t(pq[8 * XS]);
                a[mt][2] = f2t(pq[4]);
                a[mt][3] = f2t(pq[8 * XS + 4]);
            }
            #pragma unroll
            for (int nt = 0; nt < 4; nt++) {
                float2 kv = *(const float2*)&bw[(32 * nh + 8 * nt + gid) * WTS + k0 + 2 * t4];
                uint32_t bb[2] = { __float_as_uint(kv.x), __float_as_uint(kv.y) };
                mma8(acc[0][nt], a[0], bb);
                mma8(acc[1][nt], a[1], bb);
            }
        }
    }

    const int pe = 2 * ((2 * t4) & 3) + ((2 * t4) >> 2);
    const int po = 2 * ((2 * t4 + 1) & 3) + ((2 * t4 + 1) >> 2);
    #pragma unroll
    for (int mt = 0; mt < 2; mt++)
        #pragma unroll
        for (int nt = 0; nt < 4; nt++) {
            int r = row0 + 32 * mw + 16 * mt + gid;
            int cb = 32 * nh + 8 * nt;
            ko[(size_t)r * HH + cb + pe]       = __uint_as_float(f2t(acc[mt][nt][0]));
            ko[(size_t)r * HH + cb + po]       = __uint_as_float(f2t(acc[mt][nt][1]));
            ko[(size_t)(r + 8) * HH + cb + pe] = __uint_as_float(f2t(acc[mt][nt][2]));
            ko[(size_t)(r + 8) * HH + cb + po] = __uint_as_float(f2t(acc[mt][nt][3]));
        }
}

// ---------------------------------------------------------------------------
// Kernel 2: causal flash attention, KV-split with FUSED combine.
// 128 threads, 3 CTAs/SM, R6 longest-first schedule. Split-0 blocks publish
// their partial via a flag; split-1 blocks spin (all 384 blocks are
// co-resident: 384 < 148*3), merge in registers, write final output.
// ---------------------------------------------------------------------------
#define QT 64
#define KT 128
#define QS 72
#define KS 72
#define SCALE 0.03125f

#define ATTN_SMEM_FLOATS (QT * QS + KT * KS)
#define ATTN_SMEM_BYTES  (ATTN_SMEM_FLOATS * 4)

__global__ __launch_bounds__(128, 3) void attn_kernel(
    const float* __restrict__ kb, float* __restrict__ out,
    float* __restrict__ part, float* __restrict__ stats, int* __restrict__ flags)
{
    extern __shared__ float sm[];
    float* sQ = sm;             // QT*QS
    float* sK = sQ + QT * QS;   // KT*KS

    const int tid = threadIdx.x;
    const int bid = blockIdx.x;
    // proven R6 schedule: longest items first, boustrophedon rank
    const int rank = (bid < 148) ? bid : ((bid < 296) ? (443 - bid) : bid);
    const int item = c_order[rank >> 3];
    const int b = rank & 7;

    int qt, j0, j1, split;
    bool is_split;
    if (item < 32) {
        qt = 16 + (item >> 1);
        split = item & 1;
        int jm = qt >> 1;
        int h = (jm + 1) >> 1;
        if (split == 0) { j0 = 0; j1 = h - 1; }
        else            { j0 = h; j1 = jm; }
        is_split = true;
    } else {
        qt = item - 32;
        split = 0;
        j0 = 0; j1 = qt >> 1;
        is_split = false;
    }
    const int jmaskg = qt >> 1;
    const int qrow0 = qt * QT;
    const float* kbase = kb + (size_t)b * TT * HH;

    const int w = tid >> 5, lane = tid & 31, gid = lane >> 2, t4 = lane & 3;
    const int srcA = (lane & ~3) | (t4 >> 1);
    const int srcB = srcA + 2;
    const bool odd = (t4 & 1);
    const int pvoff = 2 * (gid & 3) + (gid >> 2);

    // load Q tile (scaled; power-of-two scale keeps tf32 bits)
    #pragma unroll
    for (int i = tid; i < QT * (HH / 4); i += 128) {
        int r = i >> 4, c4 = i & 15;
        float4 v = *(const float4*)(kbase + (size_t)(qrow0 + r) * HH + c4 * 4);
        v.x *= SCALE; v.y *= SCALE; v.z *= SCALE; v.w *= SCALE;
        *(float4*)&sQ[r * QS + c4 * 4] = v;
    }

    float m0 = -1e30f, m1 = -1e30f, l0 = 0.f, l1 = 0.f;
    const int rg0 = qrow0 + 16 * w + gid;
    const int rg1 = rg0 + 8;

    float o[8][4];
    #pragma unroll
    for (int i = 0; i < 8; i++)
        #pragma unroll
        for (int l = 0; l < 4; l++) o[i][l] = 0.f;

    for (int j = j0; j <= j1; j++) {
        __syncthreads();
        #pragma unroll
        for (int i = tid; i < KT * (HH / 4); i += 128) {
            int r = i >> 4, c4 = i & 15;
            *(float4*)&sK[r * KS + c4 * 4] =
                *(const float4*)(kbase + (size_t)(j * KT + r) * HH + c4 * 4);
        }
        __syncthreads();

        // ---- S = Q K^T ----
        float s[16][4];
        #pragma unroll
        for (int nt = 0; nt < 16; nt++)
            #pragma unroll
            for (int l = 0; l < 4; l++) s[nt][l] = 0.f;

        #pragma unroll
        for (int k0 = 0; k0 < HH; k0 += 8) {
            uint32_t a[4];
            float2 qa = *(const float2*)&sQ[(16 * w + gid) * QS + k0 + 2 * t4];
            float2 qb = *(const float2*)&sQ[(16 * w + gid + 8) * QS + k0 + 2 * t4];
            a[0] = __float_as_uint(qa.x);
            a[1] = __float_as_uint(qb.x);
            a[2] = __float_as_uint(qa.y);
            a[3] = __float_as_uint(qb.y);
            #pragma unroll
            for (int nt = 0; nt < 16; nt++) {
                float2 kv = *(const float2*)&sK[(8 * nt + gid) * KS + k0 + 2 * t4];
                uint32_t bb[2] = { __float_as_uint(kv.x), __float_as_uint(kv.y) };
                mma8(s[nt], a, bb);
            }
        }

        // ---- causal mask (diagonal tile only) ----
        if (j == jmaskg) {
            #pragma unroll
            for (int nt = 0; nt < 16; nt++) {
                int kc = j * KT + 8 * nt + 2 * t4;
                if (kc     > rg0) s[nt][0] = -1e30f;
                if (kc + 1 > rg0) s[nt][1] = -1e30f;
                if (kc     > rg1) s[nt][2] = -1e30f;
                if (kc + 1 > rg1) s[nt][3] = -1e30f;
            }
        }

        // ---- online softmax ----
        float mx0 = -1e30f, mx1 = -1e30f;
        #pragma unroll
        for (int nt = 0; nt < 16; nt++) {
            mx0 = fmaxf(mx0, fmaxf(s[nt][0], s[nt][1]));
            mx1 = fmaxf(mx1, fmaxf(s[nt][2], s[nt][3]));
        }
        mx0 = fmaxf(mx0, __shfl_xor_sync(0xffffffffu, mx0, 1));
        mx0 = fmaxf(mx0, __shfl_xor_sync(0xffffffffu, mx0, 2));
        mx1 = fmaxf(mx1, __shfl_xor_sync(0xffffffffu, mx1, 1));
        mx1 = fmaxf(mx1, __shfl_xor_sync(0xffffffffu, mx1, 2));

        float mn0 = fmaxf(m0, mx0), mn1 = fmaxf(m1, mx1);
        float al0 = __expf(m0 - mn0), al1 = __expf(m1 - mn1);
        m0 = mn0; m1 = mn1;

        float sum0 = 0.f, sum1 = 0.f;
        #pragma unroll
        for (int nt = 0; nt < 16; nt++) {
            s[nt][0] = __expf(s[nt][0] - mn0);
            s[nt][1] = __expf(s[nt][1] - mn0);
            s[nt][2] = __expf(s[nt][2] - mn1);
            s[nt][3] = __expf(s[nt][3] - mn1);
            sum0 += s[nt][0] + s[nt][1];
            sum1 += s[nt][2] + s[nt][3];
        }
        sum0 += __shfl_xor_sync(0xffffffffu, sum0, 1);
        sum0 += __shfl_xor_sync(0xffffffffu, sum0, 2);
        sum1 += __shfl_xor_sync(0xffffffffu, sum1, 1);
        sum1 += __shfl_xor_sync(0xffffffffu, sum1, 2);
        l0 = l0 * al0 + sum0;
        l1 = l1 * al1 + sum1;

        #pragma unroll
        for (int nt = 0; nt < 8; nt++) {
            o[nt][0] *= al0; o[nt][1] *= al0; o[nt][2] *= al1; o[nt][3] *= al1;
        }

        // ---- O += P V ----
        #pragma unroll
        for (int kk = 0; kk < 16; kk++) {
            float v00 = __shfl_sync(0xffffffffu, s[kk][0], srcA);
            float v01 = __shfl_sync(0xffffffffu, s[kk][1], srcA);
            float v10 = __shfl_sync(0xffffffffu, s[kk][0], srcB);
            float v11 = __shfl_sync(0xffffffffu, s[kk][1], srcB);
            float v20 = __shfl_sync(0xffffffffu, s[kk][2], srcA);
            float v21 = __shfl_sync(0xffffffffu, s[kk][3], srcA);
            float v30 = __shfl_sync(0xffffffffu, s[kk][2], srcB);
            float v31 = __shfl_sync(0xffffffffu, s[kk][3], srcB);
            uint32_t a[4];
            a[0] = f2t(odd ? v01 : v00);
            a[1] = f2t(odd ? v21 : v20);
            a[2] = f2t(odd ? v11 : v10);
            a[3] = f2t(odd ? v31 : v30);
            const float* rowp = sK + (8 * kk + t4) * KS + pvoff;
            #pragma unroll
            for (int nt = 0; nt < 8; nt++) {
                uint32_t bb[2] = { __float_as_uint(rowp[8 * nt]),
                                   __float_as_uint(rowp[8 * nt + 4 * KS]) };
                mma8(o[nt], a, bb);
            }
        }
    }

    const int lr0 = 16 * w + gid, lr1 = lr0 + 8;

    if (!is_split) {
        // -------- unsplit: normalize and store --------
        float il0 = 1.f / l0, il1 = 1.f / l1;
        float* ob = out + (size_t)b * TT * HH;
        #pragma unroll
        for (int nt = 0; nt < 8; nt++) {
            int c = 8 * nt + 2 * t4;
            float2 r0v = { o[nt][0] * il0, o[nt][1] * il0 };
            float2 r1v = { o[nt][2] * il1, o[nt][3] * il1 };
            *(float2*)(ob + (size_t)rg0 * HH + c) = r0v;
            *(float2*)(ob + (size_t)rg1 * HH + c) = r1v;
        }
    } else if (split == 0) {
        // -------- split-0: publish partial, then raise flag --------
        const int pair = b * 16 + (qt - 16);
        float* po = part + (size_t)pair * (QT * HH);
        #pragma unroll
        for (int nt = 0; nt < 8; nt++) {
            int c = 8 * nt + 2 * t4;
            float2 r0v = { o[nt][0], o[nt][1] };
            float2 r1v = { o[nt][2], o[nt][3] };
            *(float2*)(po + lr0 * HH + c) = r0v;
            *(float2*)(po + lr1 * HH + c) = r1v;
        }
        if (t4 == 0) {
            stats[pair * 128 + lr0 * 2]     = m0;
            stats[pair * 128 + lr0 * 2 + 1] = l0;
            stats[pair * 128 + lr1 * 2]     = m1;
            stats[pair * 128 + lr1 * 2 + 1] = l1;
        }
        __syncthreads();
        if (tid == 0) {
            __threadfence();
            atomicExch(&flags[pair], 1);
        }
    } else {
        // -------- split-1: wait for split-0, merge in registers, store --------
        const int pair = b * 16 + (qt - 16);
        if (tid == 0) {
            while (atomicAdd(&flags[pair], 0) == 0) __nanosleep(32);
        }
        __syncthreads();
        __threadfence();

        const float* po = part + (size_t)pair * (QT * HH);
        float2 st0 = __ldcg((const float2*)&stats[pair * 128 + lr0 * 2]); // (ma, la)
        float2 st1 = __ldcg((const float2*)&stats[pair * 128 + lr1 * 2]);

        float mm0 = fmaxf(st0.x, m0);
        float a00 = __expf(st0.x - mm0), a01 = __expf(m0 - mm0);
        float iv0 = 1.f / (a00 * st0.y + a01 * l0);
        float mm1 = fmaxf(st1.x, m1);
        float a10 = __expf(st1.x - mm1), a11 = __expf(m1 - mm1);
        float iv1 = 1.f / (a10 * st1.y + a11 * l1);

        float* ob = out + (size_t)b * TT * HH;
        #pragma unroll
        for (int nt = 0; nt < 8; nt++) {
            int c = 8 * nt + 2 * t4;
            float2 ua = __ldcg((const float2*)(po + lr0 * HH + c));
            float2 ub = __ldcg((const float2*)(po + lr1 * HH + c));
            float2 r0v = { (a00 * ua.x + a01 * o[nt][0]) * iv0,
                           (a00 * ua.y + a01 * o[nt][1]) * iv0 };
            float2 r1v = { (a10 * ub.x + a11 * o[nt][2]) * iv1,
                           (a10 * ub.y + a11 * o[nt][3]) * iv1 };
            *(float2*)(ob + (size_t)rg0 * HH + c) = r0v;
            *(float2*)(ob + (size_t)rg1 * HH + c) = r1v;
        }
        __syncthreads();
        if (tid == 0) flags[pair] = 0;   // restore invariant for next replay
    }
}

// ---------------------------------------------------------------------------
// launch
// ---------------------------------------------------------------------------
extern "C" void kernel_launch(void* const* d_in, const int* in_sizes, int n_in,
                              void* d_out, int out_size)
{
    const float* x = (const float*)d_in[0];   // [B, T, C]
    const float* W = (const float*)d_in[1];   // [H, C]
    float* out = (float*)d_out;               // [B, T, H]

    float *kbuf = nullptr, *wt = nullptr, *part = nullptr, *stats = nullptr;
    int* flags = nullptr;
    cudaGetSymbolAddress((void**)&kbuf, g_kbuf);
    cudaGetSymbolAddress((void**)&wt, g_wt);
    cudaGetSymbolAddress((void**)&part, g_part);
    cudaGetSymbolAddress((void**)&stats, g_stats);
    cudaGetSymbolAddress((void**)&flags, g_flags);

    cudaFuncSetAttribute(proj_kernel, cudaFuncAttributeMaxDynamicSharedMemorySize,
                         PROJ_SMEM_BYTES);
    cudaFuncSetAttribute(attn_kernel, cudaFuncAttributeMaxDynamicSharedMemorySize,
                         ATTN_SMEM_BYTES);

    wconv_kernel<<<HH, 256>>>(W, wt);

    proj_kernel<<<(BB * TT) / PROJ_M, 256, PROJ_SMEM_BYTES>>>(x, wt, kbuf);

    attn_kernel<<<384, 128, ATTN_SMEM_BYTES>>>(kbuf, out, part, stats, flags);
}

// round 10
// speedup vs baseline: 1.5645x; 1.4616x over previous
#include <cuda_runtime.h>
#include <cuda_fp16.h>
#include <cstdint>

// Problem constants
#define BB 8
#define TT 2048
#define CC 1024
#define HH 64

// k projection scratch: fp16, NATURAL layout (ldmatrix does the lane mapping)
__device__ __half g_kbuf[BB * TT * HH];
// W pre-converted to tf32 bits, pair-interleaved within 8-col k-groups (proj only)
__device__ float g_wt[HH * CC];
// KV-split partials (split-0) + per-row (m,l) + ready flags
__device__ float g_part[128 * 64 * 64];
__device__ float g_stats[128 * 64 * 2];
__device__ int g_flags[128];

// item order sorted by iteration count (descending), 48 items per batch
__constant__ int c_order[48] = {
    46,47,25,27,28,29,30,31,                 // 8 iters
    44,45,17,19,20,21,22,23,24,26,           // 7
    42,43, 9,11,12,13,14,15,16,18,           // 6
    40,41, 1, 3, 4, 5, 6, 7, 8,10,           // 5
    38,39, 0, 2,                             // 4
    36,37, 34,35, 32,33                      // 3,2,1
};

// ---------------------------------------------------------------------------
// helpers
// ---------------------------------------------------------------------------
__device__ __forceinline__ uint32_t f2t(float x) {
    uint32_t u;
    asm("cvt.rna.tf32.f32 %0, %1;" : "=r"(u) : "f"(x));
    return u;
}

__device__ __forceinline__ void mma8(float* c, const uint32_t* a, const uint32_t* b) {
    asm volatile(
        "mma.sync.aligned.m16n8k8.row.col.f32.tf32.tf32.f32 "
        "{%0,%1,%2,%3}, {%4,%5,%6,%7}, {%8,%9}, {%0,%1,%2,%3};"
        : "+f"(c[0]), "+f"(c[1]), "+f"(c[2]), "+f"(c[3])
        : "r"(a[0]), "r"(a[1]), "r"(a[2]), "r"(a[3]), "r"(b[0]), "r"(b[1]));
}

__device__ __forceinline__ void mma16(float* c, const uint32_t* a,
                                      uint32_t b0, uint32_t b1) {
    asm volatile(
        "mma.sync.aligned.m16n8k16.row.col.f32.f16.f16.f32 "
        "{%0,%1,%2,%3}, {%4,%5,%6,%7}, {%8,%9}, {%0,%1,%2,%3};"
        : "+f"(c[0]), "+f"(c[1]), "+f"(c[2]), "+f"(c[3])
        : "r"(a[0]), "r"(a[1]), "r"(a[2]), "r"(a[3]), "r"(b0), "r"(b1));
}

__device__ __forceinline__ void ldsm4(uint32_t& r0, uint32_t& r1, uint32_t& r2,
                                      uint32_t& r3, uint32_t addr) {
    asm volatile("ldmatrix.sync.aligned.m8n8.x4.shared.b16 {%0,%1,%2,%3}, [%4];"
                 : "=r"(r0), "=r"(r1), "=r"(r2), "=r"(r3) : "r"(addr));
}

__device__ __forceinline__ void ldsm4t(uint32_t& r0, uint32_t& r1, uint32_t& r2,
                                       uint32_t& r3, uint32_t addr) {
    asm volatile("ldmatrix.sync.aligned.m8n8.x4.trans.shared.b16 {%0,%1,%2,%3}, [%4];"
                 : "=r"(r0), "=r"(r1), "=r"(r2), "=r"(r3) : "r"(addr));
}

__device__ __forceinline__ uint32_t packh2(float lo, float hi) {
    uint32_t d;
    asm("cvt.rn.f16x2.f32 %0, %1, %2;" : "=r"(d) : "f"(hi), "f"(lo));
    return d;
}

__device__ __forceinline__ float ex2f(float x) {
    float y;
    asm("ex2.approx.ftz.f32 %0, %1;" : "=f"(y) : "f"(x));
    return y;
}

__device__ __forceinline__ void cpa16(uint32_t dst, const void* src) {
    asm volatile("cp.async.cg.shared.global [%0], [%1], 16;" :: "r"(dst), "l"(src));
}
__device__ __forceinline__ void cpa_commit() {
    asm volatile("cp.async.commit_group;");
}

// ---------------------------------------------------------------------------
// Kernel 0: W [64,1024] fp32 -> tf32 bits, pair-interleaved in 8-col groups.
// ---------------------------------------------------------------------------
__global__ __launch_bounds__(256) void wconv_kernel(
    const float* __restrict__ W, float* __restrict__ wt)
{
    const int row = blockIdx.x;
    const int t = threadIdx.x;
    float4 v = *(const float4*)(W + (size_t)row * CC + t * 4);
    int g = t >> 1;
    int w8b = (t & 1) * 4;
    float* dst = wt + (size_t)row * CC + g * 8;
    dst[2 * ((w8b + 0) & 3) + ((w8b + 0) >> 2)] = __uint_as_float(f2t(v.x));
    dst[2 * ((w8b + 1) & 3) + ((w8b + 1) >> 2)] = __uint_as_float(f2t(v.y));
    dst[2 * ((w8b + 2) & 3) + ((w8b + 2) >> 2)] = __uint_as_float(f2t(v.z));
    dst[2 * ((w8b + 3) & 3) + ((w8b + 3) >> 2)] = __uint_as_float(f2t(v.w));
}

// ---------------------------------------------------------------------------
// Kernel 1: k = fp16(x @ W^T). Same tf32 mainloop as R6; epilogue stores half2.
// ---------------------------------------------------------------------------
#define PROJ_M 128
#define PKC 32
#define XS 36
#define WTS 40
#define PST 4
#define PROJ_XSF (PROJ_M * XS)
#define PROJ_WSF (HH * WTS)
#define PROJ_STF (PROJ_XSF + PROJ_WSF)
#define PROJ_SMEM_BYTES (PST * PROJ_STF * 4)

__global__ __launch_bounds__(256, 1) void proj_kernel(
    const float* __restrict__ x, const float* __restrict__ wt, __half* __restrict__ ko)
{
    extern __shared__ float psm[];
    const uint32_t sba = (uint32_t)__cvta_generic_to_shared(psm);

    const int tid = threadIdx.x;
    const int row0 = blockIdx.x * PROJ_M;
    const int w = tid >> 5, lane = tid & 31, gid = lane >> 2, t4 = lane & 3;
    const int mw = w & 3;
    const int nh = w >> 2;

    const int xr[4] = { tid >> 3, (tid + 256) >> 3, (tid + 512) >> 3, (tid + 768) >> 3 };
    const int xc = tid & 7;
    const int wr0 = tid >> 3, wr1 = (tid + 256) >> 3;
    const int wc = tid & 7;

    auto issue_chunk = [&](int ci) {
        int st = ci & (PST - 1);
        uint32_t dx = sba + (uint32_t)(st * PROJ_STF) * 4;
        uint32_t dw = dx + (uint32_t)PROJ_XSF * 4;
        const float* xsrc = x + (size_t)row0 * CC + ci * PKC;
        const float* wsrc = wt + ci * PKC;
        #pragma unroll
        for (int t = 0; t < 4; t++)
            cpa16(dx + (uint32_t)(xr[t] * XS + xc * 4) * 4,
                  xsrc + (size_t)xr[t] * CC + xc * 4);
        cpa16(dw + (uint32_t)(wr0 * WTS + wc * 4) * 4, wsrc + (size_t)wr0 * CC + wc * 4);
        cpa16(dw + (uint32_t)(wr1 * WTS + wc * 4) * 4, wsrc + (size_t)wr1 * CC + wc * 4);
    };

    float acc[2][4][4];
    #pragma unroll
    for (int m = 0; m < 2; m++)
        #pragma unroll
        for (int i = 0; i < 4; i++)
            #pragma unroll
            for (int l = 0; l < 4; l++) acc[m][i][l] = 0.f;

    issue_chunk(0); cpa_commit();
    issue_chunk(1); cpa_commit();
    issue_chunk(2); cpa_commit();

    const int NCHUNK = CC / PKC;
    for (int ci = 0; ci < NCHUNK; ci++) {
        asm volatile("cp.async.wait_group 2;");
        __syncthreads();
        if (ci + 3 < NCHUNK) issue_chunk(ci + 3);
        cpa_commit();

        const float* bx = psm + (ci & (PST - 1)) * PROJ_STF;
        const float* bw = bx + PROJ_XSF;
        #pragma unroll
        for (int k0 = 0; k0 < PKC; k0 += 8) {
            uint32_t a[2][4];
            #pragma unroll
            for (int mt = 0; mt < 2; mt++) {
                const float* pq = bx + (32 * mw + 16 * mt + gid) * XS + k0 + t4;
                a[mt][0] = f2t(pq[0]);
                a[mt][1] = f2t(pq[8 * XS]);
                a[mt][2] = f2t(pq[4]);
                a[mt][3] = f2t(pq[8 * XS + 4]);
            }
            #pragma unroll
            for (int nt = 0; nt < 4; nt++) {
                float2 kv = *(const float2*)&bw[(32 * nh + 8 * nt + gid) * WTS + k0 + 2 * t4];
                uint32_t bb[2] = { __float_as_uint(kv.x), __float_as_uint(kv.y) };
                mma8(acc[0][nt], a[0], bb);
                mma8(acc[1][nt], a[1], bb);
            }
        }
    }

    // epilogue: fp16, natural columns
    #pragma unroll
    for (int mt = 0; mt < 2; mt++)
        #pragma unroll
        for (int nt = 0; nt < 4; nt++) {
            int r = row0 + 32 * mw + 16 * mt + gid;
            int cb = 32 * nh + 8 * nt + 2 * t4;
            __half2 h01 = __floats2half2_rn(acc[mt][nt][0], acc[mt][nt][1]);
            __half2 h23 = __floats2half2_rn(acc[mt][nt][2], acc[mt][nt][3]);
            *(__half2*)(ko + (size_t)r * HH + cb)       = h01;
            *(__half2*)(ko + (size_t)(r + 8) * HH + cb) = h23;
        }
}

// ---------------------------------------------------------------------------
// Kernel 2: causal flash attention, fp16 + m16n8k16 + ldmatrix, fused combine.
// 128 threads, 3 CTAs/SM, R6 longest-first schedule. Scale folded into exp.
// ---------------------------------------------------------------------------
#define QT 64
#define KT 128
#define QS2 72
#define KS2 72
#define C1 0.0450842200277801f   // log2(e) / 32

#define ATTN_SMEM_BYTES ((QT * QS2 + KT * KS2) * 2)

__global__ __launch_bounds__(128, 3) void attn_kernel(
    const __half* __restrict__ kb, float* __restrict__ out,
    float* __restrict__ part, float* __restrict__ stats, int* __restrict__ flags)
{
    extern __shared__ __half smh[];
    __half* sQ = smh;                 // QT x QS2
    __half* sK = smh + QT * QS2;      // KT x KS2
    const uint32_t sQa = (uint32_t)__cvta_generic_to_shared(sQ);
    const uint32_t sKa = (uint32_t)__cvta_generic_to_shared(sK);

    const int tid = threadIdx.x;
    const int bid = blockIdx.x;
    const int rank = (bid < 148) ? bid : ((bid < 296) ? (443 - bid) : bid);
    const int item = c_order[rank >> 3];
    const int b = rank & 7;

    int qt, j0, j1, split;
    bool is_split;
    if (item < 32) {
        qt = 16 + (item >> 1);
        split = item & 1;
        int jm = qt >> 1;
        int h = (jm + 1) >> 1;
        if (split == 0) { j0 = 0; j1 = h - 1; }
        else            { j0 = h; j1 = jm; }
        is_split = true;
    } else {
        qt = item - 32;
        split = 0;
        j0 = 0; j1 = qt >> 1;
        is_split = false;
    }
    const int jmaskg = qt >> 1;
    const int qrow0 = qt * QT;
    const __half* kbase = kb + (size_t)b * TT * HH;

    const int w = tid >> 5, lane = tid & 31, gid = lane >> 2, t4 = lane & 3;

    // ldmatrix per-lane base addresses (bytes)
    const uint32_t aQ_lane = sQa +
        (uint32_t)((16 * w + (lane & 15)) * QS2 + ((lane >> 4) << 3)) * 2;
    const uint32_t bK_lane = sKa +
        (uint32_t)((((lane & 7) + ((lane & 16) ? 8 : 0)) * KS2) + ((lane & 8) ? 8 : 0)) * 2;
    const uint32_t vV_lane = sKa +
        (uint32_t)((((lane & 7) + ((lane & 8) ? 8 : 0)) * KS2) + ((lane & 16) ? 8 : 0)) * 2;

    // load Q tile (plain copy; 1/32 scale folded into exp via C1)
    #pragma unroll
    for (int i = tid; i < QT * (HH / 8); i += 128) {
        int r = i >> 3, c = i & 7;
        *(uint4*)&sQ[r * QS2 + c * 8] =
            *(const uint4*)(kbase + (size_t)(qrow0 + r) * HH + c * 8);
    }

    float m0 = -1e30f, m1 = -1e30f, l0 = 0.f, l1 = 0.f;
    const int rg0 = qrow0 + 16 * w + gid;
    const int rg1 = rg0 + 8;

    float o[8][4];
    #pragma unroll
    for (int i = 0; i < 8; i++)
        #pragma unroll
        for (int l = 0; l < 4; l++) o[i][l] = 0.f;

    for (int j = j0; j <= j1; j++) {
        __syncthreads();
        #pragma unroll
        for (int i = tid; i < KT * (HH / 8); i += 128) {
            int r = i >> 3, c = i & 7;
            *(uint4*)&sK[r * KS2 + c * 8] =
                *(const uint4*)(kbase + (size_t)(j * KT + r) * HH + c * 8);
        }
        __syncthreads();

        // ---- S = Q K^T : fp16 m16n8k16, frags via ldmatrix ----
        float s[16][4];
        #pragma unroll
        for (int nt = 0; nt < 16; nt++)
            #pragma unroll
            for (int l = 0; l < 4; l++) s[nt][l] = 0.f;

        #pragma unroll
        for (int c = 0; c < 4; c++) {          // k-steps of 16
            uint32_t a[4];
            ldsm4(a[0], a[1], a[2], a[3], aQ_lane + c * 32);
            #pragma unroll
            for (int a8 = 0; a8 < 8; a8++) {   // 16-key groups
                uint32_t b0, b1, b2, b3;
                ldsm4(b0, b1, b2, b3,
                      bK_lane + (uint32_t)(a8 * 16 * KS2) * 2 + c * 32);
                mma16(s[2 * a8],     a, b0, b1);
                mma16(s[2 * a8 + 1], a, b2, b3);
            }
        }

        // ---- causal mask (diagonal tile only) ----
        if (j == jmaskg) {
            #pragma unroll
            for (int nt = 0; nt < 16; nt++) {
                int kc = j * KT + 8 * nt + 2 * t4;
                if (kc     > rg0) s[nt][0] = -1e30f;
                if (kc + 1 > rg0) s[nt][1] = -1e30f;
                if (kc     > rg1) s[nt][2] = -1e30f;
                if (kc + 1 > rg1) s[nt][3] = -1e30f;
            }
        }

        // ---- online softmax (scale folded: P = 2^((s - mn) * C1)) ----
        float mx0 = -1e30f, mx1 = -1e30f;
        #pragma unroll
        for (int nt = 0; nt < 16; nt++) {
            mx0 = fmaxf(mx0, fmaxf(s[nt][0], s[nt][1]));
            mx1 = fmaxf(mx1, fmaxf(s[nt][2], s[nt][3]));
        }
        mx0 = fmaxf(mx0, __shfl_xor_sync(0xffffffffu, mx0, 1));
        mx0 = fmaxf(mx0, __shfl_xor_sync(0xffffffffu, mx0, 2));
        mx1 = fmaxf(mx1, __shfl_xor_sync(0xffffffffu, mx1, 1));
        mx1 = fmaxf(mx1, __shfl_xor_sync(0xffffffffu, mx1, 2));

        float mn0 = fmaxf(m0, mx0), mn1 = fmaxf(m1, mx1);
        float al0 = ex2f((m0 - mn0) * C1), al1 = ex2f((m1 - mn1) * C1);
        m0 = mn0; m1 = mn1;
        float mc0 = mn0 * C1, mc1 = mn1 * C1;

        float sum0 = 0.f, sum1 = 0.f;
        #pragma unroll
        for (int nt = 0; nt < 16; nt++) {
            s[nt][0] = ex2f(s[nt][0] * C1 - mc0);
            s[nt][1] = ex2f(s[nt][1] * C1 - mc0);
            s[nt][2] = ex2f(s[nt][2] * C1 - mc1);
            s[nt][3] = ex2f(s[nt][3] * C1 - mc1);
            sum0 += s[nt][0] + s[nt][1];
            sum1 += s[nt][2] + s[nt][3];
        }
        sum0 += __shfl_xor_sync(0xffffffffu, sum0, 1);
        sum0 += __shfl_xor_sync(0xffffffffu, sum0, 2);
        sum1 += __shfl_xor_sync(0xffffffffu, sum1, 1);
        sum1 += __shfl_xor_sync(0xffffffffu, sum1, 2);
        l0 = l0 * al0 + sum0;
        l1 = l1 * al1 + sum1;

        #pragma unroll
        for (int nt = 0; nt < 8; nt++) {
            o[nt][0] *= al0; o[nt][1] *= al0; o[nt][2] *= al1; o[nt][3] *= al1;
        }

        // ---- O += P V : C-frag feeds A-frag directly (no shuffles) ----
        #pragma unroll
        for (int kk = 0; kk < 8; kk++) {       // 16-key groups
            uint32_t pa[4];
            pa[0] = packh2(s[2 * kk][0],     s[2 * kk][1]);
            pa[1] = packh2(s[2 * kk][2],     s[2 * kk][3]);
            pa[2] = packh2(s[2 * kk + 1][0], s[2 * kk + 1][1]);
            pa[3] = packh2(s[2 * kk + 1][2], s[2 * kk + 1][3]);
            #pragma unroll
            for (int a2 = 0; a2 < 4; a2++) {   // 16-col groups of H
                uint32_t v0, v1, v2, v3;
                ldsm4t(v0, v1, v2, v3,
                       vV_lane + (uint32_t)(kk * 16 * KS2) * 2 + a2 * 32);
                mma16(o[2 * a2],     pa, v0, v1);
                mma16(o[2 * a2 + 1], pa, v2, v3);
            }
        }
    }

    const int lr0 = 16 * w + gid, lr1 = lr0 + 8;

    if (!is_split) {
        float il0 = 1.f / l0, il1 = 1.f / l1;
        float* ob = out + (size_t)b * TT * HH;
        #pragma unroll
        for (int nt = 0; nt < 8; nt++) {
            int c = 8 * nt + 2 * t4;
            float2 r0v = { o[nt][0] * il0, o[nt][1] * il0 };
            float2 r1v = { o[nt][2] * il1, o[nt][3] * il1 };
            *(float2*)(ob + (size_t)rg0 * HH + c) = r0v;
            *(float2*)(ob + (size_t)rg1 * HH + c) = r1v;
        }
    } else if (split == 0) {
        const int pair = b * 16 + (qt - 16);
        float* po = part + (size_t)pair * (QT * HH);
        #pragma unroll
        for (int nt = 0; nt < 8; nt++) {
            int c = 8 * nt + 2 * t4;
            float2 r0v = { o[nt][0], o[nt][1] };
            float2 r1v = { o[nt][2], o[nt][3] };
            *(float2*)(po + lr0 * HH + c) = r0v;
            *(float2*)(po + lr1 * HH + c) = r1v;
        }
        if (t4 == 0) {
            stats[pair * 128 + lr0 * 2]     = m0;
            stats[pair * 128 + lr0 * 2 + 1] = l0;
            stats[pair * 128 + lr1 * 2]     = m1;
            stats[pair * 128 + lr1 * 2 + 1] = l1;
        }
        __syncthreads();
        if (tid == 0) {
            __threadfence();
            atomicExch(&flags[pair], 1);
        }
    } else {
        const int pair = b * 16 + (qt - 16);
        if (tid == 0) {
            while (atomicAdd(&flags[pair], 0) == 0) __nanosleep(32);
        }
        __syncthreads();
        __threadfence();

        const float* po = part + (size_t)pair * (QT * HH);
        float2 st0 = __ldcg((const float2*)&stats[pair * 128 + lr0 * 2]);
        float2 st1 = __ldcg((const float2*)&stats[pair * 128 + lr1 * 2]);

        float mm0 = fmaxf(st0.x, m0);
        float a00 = ex2f((st0.x - mm0) * C1), a01 = ex2f((m0 - mm0) * C1);
        float iv0 = 1.f / (a00 * st0.y + a01 * l0);
        float mm1 = fmaxf(st1.x, m1);
        float a10 = ex2f((st1.x - mm1) * C1), a11 = ex2f((m1 - mm1) * C1);
        float iv1 = 1.f / (a10 * st1.y + a11 * l1);

        float* ob = out + (size_t)b * TT * HH;
        #pragma unroll
        for (int nt = 0; nt < 8; nt++) {
            int c = 8 * nt + 2 * t4;
            float2 ua = __ldcg((const float2*)(po + lr0 * HH + c));
            float2 ub = __ldcg((const float2*)(po + lr1 * HH + c));
            float2 r0v = { (a00 * ua.x + a01 * o[nt][0]) * iv0,
                           (a00 * ua.y + a01 * o[nt][1]) * iv0 };
            float2 r1v = { (a10 * ub.x + a11 * o[nt][2]) * iv1,
                           (a10 * ub.y + a11 * o[nt][3]) * iv1 };
            *(float2*)(ob + (size_t)rg0 * HH + c) = r0v;
            *(float2*)(ob + (size_t)rg1 * HH + c) = r1v;
        }
        __syncthreads();
        if (tid == 0) flags[pair] = 0;
    }
}

// ---------------------------------------------------------------------------
// launch
// ---------------------------------------------------------------------------
extern "C" void kernel_launch(void* const* d_in, const int* in_sizes, int n_in,
                              void* d_out, int out_size)
{
    const float* x = (const float*)d_in[0];   // [B, T, C]
    const float* W = (const float*)d_in[1];   // [H, C]
    float* out = (float*)d_out;               // [B, T, H]

    __half* kbuf = nullptr;
    float *wt = nullptr, *part = nullptr, *stats = nullptr;
    int* flags = nullptr;
    cudaGetSymbolAddress((void**)&kbuf, g_kbuf);
    cudaGetSymbolAddress((void**)&wt, g_wt);
    cudaGetSymbolAddress((void**)&part, g_part);
    cudaGetSymbolAddress((void**)&stats, g_stats);
    cudaGetSymbolAddress((void**)&flags, g_flags);

    cudaFuncSetAttribute(proj_kernel, cudaFuncAttributeMaxDynamicSharedMemorySize,
                         PROJ_SMEM_BYTES);
    cudaFuncSetAttribute(attn_kernel, cudaFuncAttributeMaxDynamicSharedMemorySize,
                         ATTN_SMEM_BYTES);

    wconv_kernel<<<HH, 256>>>(W, wt);

    proj_kernel<<<(BB * TT) / PROJ_M, 256, PROJ_SMEM_BYTES>>>(x, wt, kbuf);

    attn_kernel<<<384, 128, ATTN_SMEM_BYTES>>>(kbuf, out, part, stats, flags);
}

// round 11
// speedup vs baseline: 1.6440x; 1.0508x over previous
#include <cuda_runtime.h>
#include <cuda_fp16.h>
#include <cstdint>

// Problem constants
#define BB 8
#define TT 2048
#define CC 1024
#define HH 64

// k projection scratch: fp16, NATURAL layout
__device__ __half g_kbuf[BB * TT * HH];
// W pre-converted to fp16, natural layout [H, C]
__device__ __half g_wt[HH * CC];
// KV-split partials (split-0) + per-row (m,l) + ready flags
__device__ float g_part[128 * 64 * 64];
__device__ float g_stats[128 * 64 * 2];
__device__ int g_flags[128];

// item order sorted by iteration count (descending), 48 items per batch
__constant__ int c_order[48] = {
    46,47,25,27,28,29,30,31,                 // 8 iters
    44,45,17,19,20,21,22,23,24,26,           // 7
    42,43, 9,11,12,13,14,15,16,18,           // 6
    40,41, 1, 3, 4, 5, 6, 7, 8,10,           // 5
    38,39, 0, 2,                             // 4
    36,37, 34,35, 32,33                      // 3,2,1
};

// ---------------------------------------------------------------------------
// helpers
// ---------------------------------------------------------------------------
__device__ __forceinline__ void mma16(float* c, const uint32_t* a,
                                      uint32_t b0, uint32_t b1) {
    asm volatile(
        "mma.sync.aligned.m16n8k16.row.col.f32.f16.f16.f32 "
        "{%0,%1,%2,%3}, {%4,%5,%6,%7}, {%8,%9}, {%0,%1,%2,%3};"
        : "+f"(c[0]), "+f"(c[1]), "+f"(c[2]), "+f"(c[3])
        : "r"(a[0]), "r"(a[1]), "r"(a[2]), "r"(a[3]), "r"(b0), "r"(b1));
}

__device__ __forceinline__ void ldsm4(uint32_t& r0, uint32_t& r1, uint32_t& r2,
                                      uint32_t& r3, uint32_t addr) {
    asm volatile("ldmatrix.sync.aligned.m8n8.x4.shared.b16 {%0,%1,%2,%3}, [%4];"
                 : "=r"(r0), "=r"(r1), "=r"(r2), "=r"(r3) : "r"(addr));
}

__device__ __forceinline__ void ldsm4t(uint32_t& r0, uint32_t& r1, uint32_t& r2,
                                       uint32_t& r3, uint32_t addr) {
    asm volatile("ldmatrix.sync.aligned.m8n8.x4.trans.shared.b16 {%0,%1,%2,%3}, [%4];"
                 : "=r"(r0), "=r"(r1), "=r"(r2), "=r"(r3) : "r"(addr));
}

__device__ __forceinline__ uint32_t packh2(float lo, float hi) {
    uint32_t d;
    asm("cvt.rn.f16x2.f32 %0, %1, %2;" : "=r"(d) : "f"(hi), "f"(lo));
    return d;
}

__device__ __forceinline__ float ex2f(float x) {
    float y;
    asm("ex2.approx.ftz.f32 %0, %1;" : "=f"(y) : "f"(x));
    return y;
}

__device__ __forceinline__ uint32_t h2ex2(uint32_t x) {
    uint32_t y;
    asm("ex2.approx.f16x2 %0, %1;" : "=r"(y) : "r"(x));
    return y;
}

__device__ __forceinline__ void cpa16(uint32_t dst, const void* src) {
    asm volatile("cp.async.cg.shared.global [%0], [%1], 16;" :: "r"(dst), "l"(src));
}
__device__ __forceinline__ void cpa_commit() {
    asm volatile("cp.async.commit_group;");
}

// ---------------------------------------------------------------------------
// Kernel 0: W [64,1024] fp32 -> fp16, natural layout.
// ---------------------------------------------------------------------------
__global__ __launch_bounds__(128) void wconv_kernel(
    const float* __restrict__ W, __half* __restrict__ wt)
{
    const int i = blockIdx.x * 128 + threadIdx.x;   // 16384 float4 tasks
    float4 v = ((const float4*)W)[i];
    __half2 h01 = __floats2half2_rn(v.x, v.y);
    __half2 h23 = __floats2half2_rn(v.z, v.w);
    ((__half2*)wt)[2 * i]     = h01;
    ((__half2*)wt)[2 * i + 1] = h23;
}

// ---------------------------------------------------------------------------
// Kernel 1: k = fp16(x @ W^T), fp16 m16n8k16 datapath.
// x fp32 in smem (A-frags: LDS.64 + cvt); W fp16 in smem (B-frags: ldmatrix).
// 128 rows/block, 256 threads = 8 warps (4m x 2n), 4-stage cp.async.
// ---------------------------------------------------------------------------
#define PROJ_M 128
#define PKC 32
#define XS 36                                   // x stage stride (floats)
#define WH 40                                   // W stage stride (halves)
#define PST 4
#define X_STAGE_BYTES (PROJ_M * XS * 4)         // 18432
#define W_STAGE_BYTES (HH * WH * 2)             // 5120
#define STAGE_BYTES (X_STAGE_BYTES + W_STAGE_BYTES)  // 23552
#define PROJ_SMEM_BYTES (PST * STAGE_BYTES)     // 94208

__global__ __launch_bounds__(256, 1) void proj_kernel(
    const float* __restrict__ x, const __half* __restrict__ wt, __half* __restrict__ ko)
{
    extern __shared__ char psm[];
    const uint32_t sba = (uint32_t)__cvta_generic_to_shared(psm);

    const int tid = threadIdx.x;
    const int row0 = blockIdx.x * PROJ_M;
    const int w = tid >> 5, lane = tid & 31, gid = lane >> 2, t4 = lane & 3;
    const int mw = w & 3;      // m-group: 32 rows at 32*mw
    const int nh = w >> 2;     // n-group: 32 cols at 32*nh

    // x loader: 1024 float4 tasks -> 4/thread; W loader: 256 16B tasks -> 1/thread
    const int xr[4] = { tid >> 3, (tid + 256) >> 3, (tid + 512) >> 3, (tid + 768) >> 3 };
    const int xc = tid & 7;
    const int wr = tid >> 2, wc = tid & 3;

    auto issue_chunk = [&](int ci) {
        int st = ci & (PST - 1);
        uint32_t dx = sba + (uint32_t)(st * STAGE_BYTES);
        uint32_t dw = dx + X_STAGE_BYTES;
        const float* xsrc = x + (size_t)row0 * CC + ci * PKC;
        const __half* wsrc = wt + ci * PKC;
        #pragma unroll
        for (int t = 0; t < 4; t++)
            cpa16(dx + (uint32_t)(xr[t] * XS + xc * 4) * 4,
                  xsrc + (size_t)xr[t] * CC + xc * 4);
        cpa16(dw + (uint32_t)(wr * WH + wc * 8) * 2, wsrc + (size_t)wr * CC + wc * 8);
    };

    // ldmatrix lane address components for W (same pattern as attn QK B side)
    const int bRow = (lane & 7) + ((lane & 16) ? 8 : 0);
    const int bColB = (lane & 8) ? 8 : 0;

    float acc[2][4][4];
    #pragma unroll
    for (int m = 0; m < 2; m++)
        #pragma unroll
        for (int i = 0; i < 4; i++)
            #pragma unroll
            for (int l = 0; l < 4; l++) acc[m][i][l] = 0.f;

    issue_chunk(0); cpa_commit();
    issue_chunk(1); cpa_commit();
    issue_chunk(2); cpa_commit();

    const int NCHUNK = CC / PKC;  // 32
    for (int ci = 0; ci < NCHUNK; ci++) {
        asm volatile("cp.async.wait_group 2;");
        __syncthreads();
        if (ci + 3 < NCHUNK) issue_chunk(ci + 3);
        cpa_commit();

        const int st = ci & (PST - 1);
        const float* bx = (const float*)(psm + st * STAGE_BYTES);
        const uint32_t bwa = sba + (uint32_t)(st * STAGE_BYTES) + X_STAGE_BYTES;

        #pragma unroll
        for (int c = 0; c < 2; c++) {          // two k16 steps per 32-k chunk
            uint32_t a[2][4];
            #pragma unroll
            for (int mt = 0; mt < 2; mt++) {
                const float* p = bx + (32 * mw + 16 * mt + gid) * XS + 16 * c + 2 * t4;
                float2 u0 = *(const float2*)p;
                float2 u1 = *(const float2*)(p + 8 * XS);
                float2 u2 = *(const float2*)(p + 8);
                float2 u3 = *(const float2*)(p + 8 * XS + 8);
                a[mt][0] = packh2(u0.x, u0.y);
                a[mt][1] = packh2(u1.x, u1.y);
                a[mt][2] = packh2(u2.x, u2.y);
                a[mt][3] = packh2(u3.x, u3.y);
            }
            #pragma unroll
            for (int g = 0; g < 2; g++) {      // two 16-n groups
                uint32_t b0, b1, b2, b3;
                uint32_t baddr = bwa +
                    (uint32_t)((32 * nh + 16 * g + bRow) * WH + 16 * c + bColB) * 2;
                ldsm4(b0, b1, b2, b3, baddr);
                mma16(acc[0][2 * g],     a[0], b0, b1);
                mma16(acc[0][2 * g + 1], a[0], b2, b3);
                mma16(acc[1][2 * g],     a[1], b0, b1);
                mma16(acc[1][2 * g + 1], a[1], b2, b3);
            }
        }
    }

    // epilogue: fp16, natural columns
    #pragma unroll
    for (int mt = 0; mt < 2; mt++)
        #pragma unroll
        for (int nt = 0; nt < 4; nt++) {
            int r = row0 + 32 * mw + 16 * mt + gid;
            int cb = 32 * nh + 8 * nt + 2 * t4;
            __half2 h01 = __floats2half2_rn(acc[mt][nt][0], acc[mt][nt][1]);
            __half2 h23 = __floats2half2_rn(acc[mt][nt][2], acc[mt][nt][3]);
            *(__half2*)(ko + (size_t)r * HH + cb)       = h01;
            *(__half2*)(ko + (size_t)(r + 8) * HH + cb) = h23;
        }
}

// ---------------------------------------------------------------------------
// Kernel 2: causal flash attention, fp16 + m16n8k16 + ldmatrix, fused combine.
// Softmax v2: exp via ex2.approx.f16x2 (P lands directly in PV A-frag layout);
// row-sum l via mma against a ones-B (exact fp32 sum of the fp16 P used in PV).
// ---------------------------------------------------------------------------
#define QT 64
#define KT 128
#define QS2 72
#define KS2 72
#define C1 0.0450842200277801f   // log2(e) / 32
#define ONESH2 0x3C003C00u

#define ATTN_SMEM_BYTES ((QT * QS2 + KT * KS2) * 2)

__global__ __launch_bounds__(128, 3) void attn_kernel(
    const __half* __restrict__ kb, float* __restrict__ out,
    float* __restrict__ part, float* __restrict__ stats, int* __restrict__ flags)
{
    extern __shared__ __half smh[];
    __half* sQ = smh;                 // QT x QS2
    __half* sK = smh + QT * QS2;      // KT x KS2
    const uint32_t sQa = (uint32_t)__cvta_generic_to_shared(sQ);
    const uint32_t sKa = (uint32_t)__cvta_generic_to_shared(sK);

    const int tid = threadIdx.x;
    const int bid = blockIdx.x;
    const int rank = (bid < 148) ? bid : ((bid < 296) ? (443 - bid) : bid);
    const int item = c_order[rank >> 3];
    const int b = rank & 7;

    int qt, j0, j1, split;
    bool is_split;
    if (item < 32) {
        qt = 16 + (item >> 1);
        split = item & 1;
        int jm = qt >> 1;
        int h = (jm + 1) >> 1;
        if (split == 0) { j0 = 0; j1 = h - 1; }
        else            { j0 = h; j1 = jm; }
        is_split = true;
    } else {
        qt = item - 32;
        split = 0;
        j0 = 0; j1 = qt >> 1;
        is_split = false;
    }
    const int jmaskg = qt >> 1;
    const int qrow0 = qt * QT;
    const __half* kbase = kb + (size_t)b * TT * HH;

    const int w = tid >> 5, lane = tid & 31, gid = lane >> 2, t4 = lane & 3;

    const uint32_t aQ_lane = sQa +
        (uint32_t)((16 * w + (lane & 15)) * QS2 + ((lane >> 4) << 3)) * 2;
    const uint32_t bK_lane = sKa +
        (uint32_t)((((lane & 7) + ((lane & 16) ? 8 : 0)) * KS2) + ((lane & 8) ? 8 : 0)) * 2;
    const uint32_t vV_lane = sKa +
        (uint32_t)((((lane & 7) + ((lane & 8) ? 8 : 0)) * KS2) + ((lane & 16) ? 8 : 0)) * 2;

    // load Q tile (plain copy; 1/32 scale folded into exp via C1)
    #pragma unroll
    for (int i = tid; i < QT * (HH / 8); i += 128) {
        int r = i >> 3, c = i & 7;
        *(uint4*)&sQ[r * QS2 + c * 8] =
            *(const uint4*)(kbase + (size_t)(qrow0 + r) * HH + c * 8);
    }

    float m0 = -1e30f, m1 = -1e30f, l0 = 0.f, l1 = 0.f;
    const int rg0 = qrow0 + 16 * w + gid;
    const int rg1 = rg0 + 8;

    float o[8][4];
    #pragma unroll
    for (int i = 0; i < 8; i++)
        #pragma unroll
        for (int l = 0; l < 4; l++) o[i][l] = 0.f;

    for (int j = j0; j <= j1; j++) {
        __syncthreads();
        #pragma unroll
        for (int i = tid; i < KT * (HH / 8); i += 128) {
            int r = i >> 3, c = i & 7;
            *(uint4*)&sK[r * KS2 + c * 8] =
                *(const uint4*)(kbase + (size_t)(j * KT + r) * HH + c * 8);
        }
        __syncthreads();

        // ---- S = Q K^T ----
        float s[16][4];
        #pragma unroll
        for (int nt = 0; nt < 16; nt++)
            #pragma unroll
            for (int l = 0; l < 4; l++) s[nt][l] = 0.f;

        #pragma unroll
        for (int c = 0; c < 4; c++) {
            uint32_t a[4];
            ldsm4(a[0], a[1], a[2], a[3], aQ_lane + c * 32);
            #pragma unroll
            for (int a8 = 0; a8 < 8; a8++) {
                uint32_t b0, b1, b2, b3;
                ldsm4(b0, b1, b2, b3,
                      bK_lane + (uint32_t)(a8 * 16 * KS2) * 2 + c * 32);
                mma16(s[2 * a8],     a, b0, b1);
                mma16(s[2 * a8 + 1], a, b2, b3);
            }
        }

        // ---- causal mask (diagonal tile only) ----
        if (j == jmaskg) {
            #pragma unroll
            for (int nt = 0; nt < 16; nt++) {
                int kc = j * KT + 8 * nt + 2 * t4;
                if (kc     > rg0) s[nt][0] = -1e30f;
                if (kc + 1 > rg0) s[nt][1] = -1e30f;
                if (kc     > rg1) s[nt][2] = -1e30f;
                if (kc + 1 > rg1) s[nt][3] = -1e30f;
            }
        }

        // ---- online softmax v2 ----
        float mx0 = -1e30f, mx1 = -1e30f;
        #pragma unroll
        for (int nt = 0; nt < 16; nt++) {
            mx0 = fmaxf(mx0, fmaxf(s[nt][0], s[nt][1]));
            mx1 = fmaxf(mx1, fmaxf(s[nt][2], s[nt][3]));
        }
        mx0 = fmaxf(mx0, __shfl_xor_sync(0xffffffffu, mx0, 1));
        mx0 = fmaxf(mx0, __shfl_xor_sync(0xffffffffu, mx0, 2));
        mx1 = fmaxf(mx1, __shfl_xor_sync(0xffffffffu, mx1, 1));
        mx1 = fmaxf(mx1, __shfl_xor_sync(0xffffffffu, mx1, 2));

        float mn0 = fmaxf(m0, mx0), mn1 = fmaxf(m1, mx1);
        float al0 = ex2f((m0 - mn0) * C1), al1 = ex2f((m1 - mn1) * C1);
        m0 = mn0; m1 = mn1;
        float mc0 = mn0 * C1, mc1 = mn1 * C1;

        // t = s*C1 - mc (fp32) -> pack half2 -> ex2.f16x2 -> P in PV A-frag layout
        uint32_t pa[8][4];
        #pragma unroll
        for (int nt = 0; nt < 16; nt++) {
            float t0 = s[nt][0] * C1 - mc0;
            float t1 = s[nt][1] * C1 - mc0;
            float t2 = s[nt][2] * C1 - mc1;
            float t3 = s[nt][3] * C1 - mc1;
            uint32_t u01 = h2ex2(packh2(t0, t1));
            uint32_t u23 = h2ex2(packh2(t2, t3));
            pa[nt >> 1][(nt & 1) * 2]     = u01;
            pa[nt >> 1][(nt & 1) * 2 + 1] = u23;
        }

        #pragma unroll
        for (int nt = 0; nt < 8; nt++) {
            o[nt][0] *= al0; o[nt][1] *= al0; o[nt][2] *= al1; o[nt][3] *= al1;
        }

        // ---- O += P V ; l-partials via mma against ones-B ----
        float lacc[4] = { 0.f, 0.f, 0.f, 0.f };
        #pragma unroll
        for (int kk = 0; kk < 8; kk++) {
            mma16(lacc, pa[kk], ONESH2, ONESH2);
            #pragma unroll
            for (int a2 = 0; a2 < 4; a2++) {
                uint32_t v0, v1, v2, v3;
                ldsm4t(v0, v1, v2, v3,
                       vV_lane + (uint32_t)(kk * 16 * KS2) * 2 + a2 * 32);
                mma16(o[2 * a2],     pa[kk], v0, v1);
                mma16(o[2 * a2 + 1], pa[kk], v2, v3);
            }
        }
        l0 = l0 * al0 + lacc[0];
        l1 = l1 * al1 + lacc[2];
    }

    const int lr0 = 16 * w + gid, lr1 = lr0 + 8;

    if (!is_split) {
        float il0 = 1.f / l0, il1 = 1.f / l1;
        float* ob = out + (size_t)b * TT * HH;
        #pragma unroll
        for (int nt = 0; nt < 8; nt++) {
            int c = 8 * nt + 2 * t4;
            float2 r0v = { o[nt][0] * il0, o[nt][1] * il0 };
            float2 r1v = { o[nt][2] * il1, o[nt][3] * il1 };
            *(float2*)(ob + (size_t)rg0 * HH + c) = r0v;
            *(float2*)(ob + (size_t)rg1 * HH + c) = r1v;
        }
    } else if (split == 0) {
        const int pair = b * 16 + (qt - 16);
        float* po = part + (size_t)pair * (QT * HH);
        #pragma unroll
        for (int nt = 0; nt < 8; nt++) {
            int c = 8 * nt + 2 * t4;
            float2 r0v = { o[nt][0], o[nt][1] };
            float2 r1v = { o[nt][2], o[nt][3] };
            *(float2*)(po + lr0 * HH + c) = r0v;
            *(float2*)(po + lr1 * HH + c) = r1v;
        }
        if (t4 == 0) {
            stats[pair * 128 + lr0 * 2]     = m0;
            stats[pair * 128 + lr0 * 2 + 1] = l0;
            stats[pair * 128 + lr1 * 2]     = m1;
            stats[pair * 128 + lr1 * 2 + 1] = l1;
        }
        __syncthreads();
        if (tid == 0) {
            __threadfence();
            atomicExch(&flags[pair], 1);
        }
    } else {
        const int pair = b * 16 + (qt - 16);
        if (tid == 0) {
            while (atomicAdd(&flags[pair], 0) == 0) __nanosleep(32);
        }
        __syncthreads();
        __threadfence();

        const float* po = part + (size_t)pair * (QT * HH);
        float2 st0 = __ldcg((const float2*)&stats[pair * 128 + lr0 * 2]);
        float2 st1 = __ldcg((const float2*)&stats[pair * 128 + lr1 * 2]);

        float mm0 = fmaxf(st0.x, m0);
        float a00 = ex2f((st0.x - mm0) * C1), a01 = ex2f((m0 - mm0) * C1);
        float iv0 = 1.f / (a00 * st0.y + a01 * l0);
        float mm1 = fmaxf(st1.x, m1);
        float a10 = ex2f((st1.x - mm1) * C1), a11 = ex2f((m1 - mm1) * C1);
        float iv1 = 1.f / (a10 * st1.y + a11 * l1);

        float* ob = out + (size_t)b * TT * HH;
        #pragma unroll
        for (int nt = 0; nt < 8; nt++) {
            int c = 8 * nt + 2 * t4;
            float2 ua = __ldcg((const float2*)(po + lr0 * HH + c));
            float2 ub = __ldcg((const float2*)(po + lr1 * HH + c));
            float2 r0v = { (a00 * ua.x + a01 * o[nt][0]) * iv0,
                           (a00 * ua.y + a01 * o[nt][1]) * iv0 };
            float2 r1v = { (a10 * ub.x + a11 * o[nt][2]) * iv1,
                           (a10 * ub.y + a11 * o[nt][3]) * iv1 };
            *(float2*)(ob + (size_t)rg0 * HH + c) = r0v;
            *(float2*)(ob + (size_t)rg1 * HH + c) = r1v;
        }
        __syncthreads();
        if (tid == 0) flags[pair] = 0;
    }
}

// ---------------------------------------------------------------------------
// launch
// ---------------------------------------------------------------------------
extern "C" void kernel_launch(void* const* d_in, const int* in_sizes, int n_in,
                              void* d_out, int out_size)
{
    const float* x = (const float*)d_in[0];   // [B, T, C]
    const float* W = (const float*)d_in[1];   // [H, C]
    float* out = (float*)d_out;               // [B, T, H]

    __half *kbuf = nullptr, *wt = nullptr;
    float *part = nullptr, *stats = nullptr;
    int* flags = nullptr;
    cudaGetSymbolAddress((void**)&kbuf, g_kbuf);
    cudaGetSymbolAddress((void**)&wt, g_wt);
    cudaGetSymbolAddress((void**)&part, g_part);
    cudaGetSymbolAddress((void**)&stats, g_stats);
    cudaGetSymbolAddress((void**)&flags, g_flags);

    cudaFuncSetAttribute(proj_kernel, cudaFuncAttributeMaxDynamicSharedMemorySize,
                         PROJ_SMEM_BYTES);
    cudaFuncSetAttribute(attn_kernel, cudaFuncAttributeMaxDynamicSharedMemorySize,
                         ATTN_SMEM_BYTES);

    wconv_kernel<<<128, 128>>>(W, wt);

    proj_kernel<<<(BB * TT) / PROJ_M, 256, PROJ_SMEM_BYTES>>>(x, wt, kbuf);

    attn_kernel<<<384, 128, ATTN_SMEM_BYTES>>>(kbuf, out, part, stats, flags);
}